// round 10
// baseline (speedup 1.0000x reference)
#include <cuda_runtime.h>
#include <cstdint>

#define S_LEN  2048
#define HEADS  32
#define DDIM   64
#define BQ     256
#define BK     64
#define NTILES (S_LEN / BK)   // 32
#define MASKW  (S_LEN / 32)   // 64 mask words per row

#define SLOTW  136                    // pair-slot stride in u32 (2*64 + 8 pad)
#define KIMG_W (16 * SLOTW)           // 2176 u32 = 8704 B (one K or V tile image)
#define TILE_W (2 * KIMG_W)           // 4352 u32 = 17408 B (K + V)
#define TILE_BYTES (TILE_W * 4)
#define SMEM_U32 (2 * TILE_W)         // 34816 B (double buffer)

__device__ uint32_t g_maskbits[S_LEN * MASKW];                 // 512 KB
__device__ uint32_t g_KVp[(size_t)HEADS * NTILES * TILE_W];    // ~17.8 MB packed K+V (fp16)

__device__ __forceinline__ uint32_t packh2(float lo, float hi) {
    uint32_t r;
    asm("cvt.rn.f16x2.f32 %0, %1, %2;" : "=r"(r) : "f"(hi), "f"(lo));
    return r;
}
__device__ __forceinline__ float ex2f(float x) {
    float r;
    asm("ex2.approx.f32 %0, %1;" : "=f"(r) : "f"(x));
    return r;
}
__device__ __forceinline__ void mma_f16(float* d, const uint32_t* a, uint32_t b0, uint32_t b1) {
    asm volatile(
        "mma.sync.aligned.m16n8k16.row.col.f32.f16.f16.f32 "
        "{%0,%1,%2,%3}, {%4,%5,%6,%7}, {%8,%9}, {%0,%1,%2,%3};"
        : "+f"(d[0]), "+f"(d[1]), "+f"(d[2]), "+f"(d[3])
        : "r"(a[0]), "r"(a[1]), "r"(a[2]), "r"(a[3]), "r"(b0), "r"(b1));
}
__device__ __forceinline__ uint32_t smem_u32(const void* p) {
    uint32_t a;
    asm("{ .reg .u64 t; cvta.to.shared.u64 t, %1; cvt.u32.u64 %0, t; }" : "=r"(a) : "l"(p));
    return a;
}
__device__ __forceinline__ void cpa16(uint32_t s, const void* g) {
    asm volatile("cp.async.cg.shared.global [%0], [%1], 16;" :: "r"(s), "l"(g));
}
#define CP_COMMIT() asm volatile("cp.async.commit_group;" ::: "memory")
#define CP_WAIT1()  asm volatile("cp.async.wait_group 1;" ::: "memory")

// ---------------- mask -> bitmask pre-pass (vectorized: 1 thread = 1 word) ----
__global__ void mask_bits_kernel(const int* __restrict__ M) {
    const int w = blockIdx.x * 256 + threadIdx.x;      // word index
    const int4* p = (const int4*)(M + (size_t)w * 32);
    uint32_t bits = 0;
    #pragma unroll
    for (int i = 0; i < 8; ++i) {
        int4 v = p[i];
        bits |= (v.x != 0 ? 1u : 0u) << (4 * i + 0);
        bits |= (v.y != 0 ? 1u : 0u) << (4 * i + 1);
        bits |= (v.z != 0 ? 1u : 0u) << (4 * i + 2);
        bits |= (v.w != 0 ? 1u : 0u) << (4 * i + 3);
    }
    g_maskbits[w] = bits;
}

// ---------------- K/V pack pre-pass: fp16 pair-slot smem images ----------------
__global__ void kv_pack_kernel(const float* __restrict__ K, const float* __restrict__ V) {
    const int t = blockIdx.x, h = blockIdx.y;
    const int tid = threadIdx.x;
    const int r = tid & 63, sg = tid >> 6;
    const float* kbT = K + (size_t)h * S_LEN * DDIM + (size_t)t * BK * DDIM;
    const float* vbT = V + (size_t)h * S_LEN * DDIM + (size_t)t * BK * DDIM;
    uint32_t* kd = g_KVp + ((size_t)h * NTILES + t) * TILE_W;
    uint32_t* vd = kd + KIMG_W;

    #pragma unroll
    for (int si = 0; si < 4; ++si) {
        const int slot = 4 * si + sg;
        const int kk = slot >> 2, tg = slot & 3;
        const int c0 = 16 * kk + 2 * tg;
        float2 ka = *(const float2*)&kbT[(size_t)r * DDIM + c0];
        float2 kc = *(const float2*)&kbT[(size_t)r * DDIM + c0 + 8];
        *(uint2*)&kd[slot * SLOTW + 2 * r] =
            make_uint2(packh2(ka.x, ka.y), packh2(kc.x, kc.y));
        float v0 = vbT[(size_t)(c0 + 0) * DDIM + r];
        float v1 = vbT[(size_t)(c0 + 1) * DDIM + r];
        float v8 = vbT[(size_t)(c0 + 8) * DDIM + r];
        float v9 = vbT[(size_t)(c0 + 9) * DDIM + r];
        *(uint2*)&vd[slot * SLOTW + 2 * r] =
            make_uint2(packh2(v0, v1), packh2(v8, v9));
    }
}

// ---------------- main kernel: M=32 per warp, b-frags reused across row-tiles ----
__global__ void __launch_bounds__(256, 1)
fa_f16w32_kernel(const float* __restrict__ Q, float* __restrict__ O) {
    __shared__ uint32_t smem[SMEM_U32];
    const uint32_t sb = smem_u32(smem);

    const int tid  = threadIdx.x;
    const int wid  = tid >> 5, lane = tid & 31;
    const int g    = lane >> 2, tg = lane & 3;
    const int bh   = blockIdx.y;
    const int q0   = blockIdx.x * BQ;
    const int rw   = wid * 32;               // warp's first local row (0..224)

    const float* qb = Q + (size_t)bh * S_LEN * DDIM;
    float*       ob = O + (size_t)bh * S_LEN * DDIM;
    const char*  kvb = (const char*)(g_KVp + (size_t)bh * NTILES * TILE_W);

    // ---- Q fragments: 2 row-tiles x 4 k-steps x 4 regs = 32 regs ----
    uint32_t qfrag[2][4][4];
    #pragma unroll
    for (int rt = 0; rt < 2; ++rt) {
        const float* qr0 = &qb[(size_t)(q0 + rw + 16 * rt + g) * DDIM];
        const float* qr1 = qr0 + 8 * DDIM;
        #pragma unroll
        for (int kk = 0; kk < 4; ++kk) {
            const int c0 = 16 * kk + 2 * tg;
            float2 x0 = *(const float2*)&qr0[c0];
            float2 x1 = *(const float2*)&qr1[c0];
            float2 x2 = *(const float2*)&qr0[c0 + 8];
            float2 x3 = *(const float2*)&qr1[c0 + 8];
            qfrag[rt][kk][0] = packh2(x0.x, x0.y);
            qfrag[rt][kk][1] = packh2(x1.x, x1.y);
            qfrag[rt][kk][2] = packh2(x2.x, x2.y);
            qfrag[rt][kk][3] = packh2(x3.x, x3.y);
        }
    }

    auto issue_kv = [&](int tile, int par) {
        const char* src = kvb + (size_t)tile * TILE_BYTES;
        const uint32_t dst = sb + par * TILE_BYTES;
        #pragma unroll
        for (int i = 0; i < 4; ++i) {
            const int c = tid + 256 * i;
            cpa16(dst + 16 * c, src + 16 * c);
        }
        if (tid < 64) {
            const int c = tid + 1024;
            cpa16(dst + 16 * c, src + 16 * c);
        }
    };

    issue_kv(0, 0); CP_COMMIT();
    issue_kv(1, 1); CP_COMMIT();

    float oacc[2][8][4];
    #pragma unroll
    for (int rt = 0; rt < 2; ++rt)
        #pragma unroll
        for (int j = 0; j < 8; ++j)
            #pragma unroll
            for (int c = 0; c < 4; ++c) oacc[rt][j][c] = 0.f;
    float lsum[2][2] = {{0.f, 0.f}, {0.f, 0.f}};

    const float EC = 0.18033688011112042f;   // 0.125 * log2(e)

    for (int t = 0; t < NTILES; ++t) {
        const int par = t & 1;
        const uint32_t* kbuf = smem + par * TILE_W;
        const uint32_t* vbuf = kbuf + KIMG_W;

        CP_WAIT1();
        __syncthreads();

        // ---- S = Q K^T : each b-frag load feeds BOTH row-tiles ----
        float sacc[2][8][4];
        #pragma unroll
        for (int rt = 0; rt < 2; ++rt)
            #pragma unroll
            for (int j = 0; j < 8; ++j)
                #pragma unroll
                for (int c = 0; c < 4; ++c) sacc[rt][j][c] = 0.f;

        #pragma unroll
        for (int kk = 0; kk < 4; ++kk) {
            const uint32_t* kp = &kbuf[(4 * kk + tg) * SLOTW + 2 * g];
            #pragma unroll
            for (int j = 0; j < 8; ++j) {
                uint2 b2 = *(const uint2*)(kp + 16 * j);
                mma_f16(sacc[0][j], qfrag[0][kk], b2.x, b2.y);
                mma_f16(sacc[1][j], qfrag[1][kk], b2.x, b2.y);
            }
        }

        // ---- mask + exp: S cols are keys {8j+2tg, 8j+2tg+1} ----
        uint2 pr[2][8];
        #pragma unroll
        for (int rt = 0; rt < 2; ++rt) {
            const int r0 = rw + 16 * rt + g;
            const uint2 mw0 = *(const uint2*)&g_maskbits[(size_t)(q0 + r0) * MASKW + 2 * t];
            const uint2 mw1 = *(const uint2*)&g_maskbits[(size_t)(q0 + r0 + 8) * MASKW + 2 * t];
            #pragma unroll
            for (int j = 0; j < 8; ++j) {
                const uint32_t w0 = (j < 4) ? mw0.x : mw0.y;
                const uint32_t w1 = (j < 4) ? mw1.x : mw1.y;
                const int sh = ((j & 3) << 3) + 2 * tg;
                float e00 = ((w0 >> sh) & 1u)       ? ex2f(sacc[rt][j][0] * EC) : 0.f;
                float e01 = ((w0 >> (sh + 1)) & 1u) ? ex2f(sacc[rt][j][1] * EC) : 0.f;
                float e10 = ((w1 >> sh) & 1u)       ? ex2f(sacc[rt][j][2] * EC) : 0.f;
                float e11 = ((w1 >> (sh + 1)) & 1u) ? ex2f(sacc[rt][j][3] * EC) : 0.f;
                lsum[rt][0] += e00 + e01;
                lsum[rt][1] += e10 + e11;
                pr[rt][j] = make_uint2(packh2(e00, e01), packh2(e10, e11));
            }
        }

        // ---- O += P V : each V b-frag load feeds BOTH row-tiles ----
        #pragma unroll
        for (int kk = 0; kk < 4; ++kk) {
            uint32_t a0[4] = { pr[0][2*kk].x, pr[0][2*kk].y, pr[0][2*kk+1].x, pr[0][2*kk+1].y };
            uint32_t a1[4] = { pr[1][2*kk].x, pr[1][2*kk].y, pr[1][2*kk+1].x, pr[1][2*kk+1].y };
            const uint32_t* vp = &vbuf[(4 * kk + tg) * SLOTW + 2 * g];
            #pragma unroll
            for (int j = 0; j < 8; ++j) {
                uint2 b2 = *(const uint2*)(vp + 16 * j);
                mma_f16(oacc[0][j], a0, b2.x, b2.y);
                mma_f16(oacc[1][j], a1, b2.x, b2.y);
            }
        }

        __syncthreads();
        if (t + 2 < NTILES) issue_kv(t + 2, par);
        CP_COMMIT();
    }

    // ---- reduce l across the 4 tg lanes, normalize, write O ----
    #pragma unroll
    for (int rt = 0; rt < 2; ++rt) {
        lsum[rt][0] += __shfl_xor_sync(0xffffffffu, lsum[rt][0], 1);
        lsum[rt][0] += __shfl_xor_sync(0xffffffffu, lsum[rt][0], 2);
        lsum[rt][1] += __shfl_xor_sync(0xffffffffu, lsum[rt][1], 1);
        lsum[rt][1] += __shfl_xor_sync(0xffffffffu, lsum[rt][1], 2);
        const float inv0 = 1.f / lsum[rt][0];
        const float inv1 = 1.f / lsum[rt][1];
        const int r0 = rw + 16 * rt + g;
        #pragma unroll
        for (int j = 0; j < 8; ++j) {
            float2 o0 = make_float2(oacc[rt][j][0] * inv0, oacc[rt][j][1] * inv0);
            float2 o1 = make_float2(oacc[rt][j][2] * inv1, oacc[rt][j][3] * inv1);
            *(float2*)&ob[(size_t)(q0 + r0) * DDIM + 8 * j + 2 * tg] = o0;
            *(float2*)&ob[(size_t)(q0 + r0 + 8) * DDIM + 8 * j + 2 * tg] = o1;
        }
    }
}

// ---------------- launch ----------------
extern "C" void kernel_launch(void* const* d_in, const int* in_sizes, int n_in,
                              void* d_out, int out_size) {
    const float* q = (const float*)d_in[0];
    const float* k = (const float*)d_in[1];
    const float* v = (const float*)d_in[2];
    const int*   m = (const int*)d_in[3];
    float* out = (float*)d_out;

    mask_bits_kernel<<<(S_LEN * MASKW) / 256, 256>>>(m);
    kv_pack_kernel<<<dim3(NTILES, HEADS), 256>>>(k, v);

    dim3 grid(S_LEN / BQ, HEADS);
    fa_f16w32_kernel<<<grid, 256>>>(q, out);
}